// round 13
// baseline (speedup 1.0000x reference)
#include <cuda_runtime.h>
#include <cuda_fp16.h>
#include <cstdint>

#define NN 100000
#define NG 512
#define IND 16
#define HID 64
#define EPS 1e-5f
#define MAXE 1200000
#define SCAN_BLOCKS 391  // ceil(NN/256)

// ---------------- device scratch ----------------
__device__ __half d_g[NN * HID];     // dis-scaled per-node messages (fp16)
__device__ __half d_accA[NN * HID];  // aggregated features (fp16)
__device__ __half d_accB[NN * HID];
__device__ int   d_deg[NN];
__device__ int   d_off[NN];
__device__ int   d_cur[NN];
__device__ int   d_csr[MAXE];
__device__ int   d_bsum[512];
__device__ int   d_bbase[512];
__device__ float d_sumIn[IND], d_sqIn[IND];
__device__ float d_sumL[3 * HID], d_sqL[3 * HID];
__device__ float d_pool[NG * HID];
__device__ int   d_cnt[NG];

// ---------------- f32x2 helpers ----------------
__device__ __forceinline__ unsigned long long pk2(float x) {
    unsigned long long r;
    asm("mov.b64 %0,{%1,%1};" : "=l"(r) : "f"(x));
    return r;
}
__device__ __forceinline__ void fma2(unsigned long long& d, unsigned long long a,
                                     unsigned long long b) {
    asm("fma.rn.f32x2 %0,%1,%2,%0;" : "+l"(d) : "l"(a), "l"(b));
}
__device__ __forceinline__ void unpk2(unsigned long long v, float& a, float& b) {
    asm("mov.b64 {%0,%1},%2;" : "=f"(a), "=f"(b) : "l"(v));
}

// ---------------- init ----------------
__global__ void k_zero() {
    int i = blockIdx.x * 256 + threadIdx.x;
    if (i < NN) { d_deg[i] = 0; d_cur[i] = 0; }
    if (i < NG * HID) d_pool[i] = 0.f;
    if (i < NG) d_cnt[i] = 0;
    if (i < 3 * HID) { d_sumL[i] = 0.f; d_sqL[i] = 0.f; }
    if (i < IND) { d_sumIn[i] = 0.f; d_sqIn[i] = 0.f; }
}

__global__ void k_deg(const int* __restrict__ dst, int E) {
    int e = blockIdx.x * 256 + threadIdx.x;
    if (e < E) atomicAdd(&d_deg[dst[e]], 1);
}

// ---------------- input batchnorm stats over x [N,16] ----------------
__global__ void k_statsIn(const float* __restrict__ x) {
    int col = threadIdx.x & 15, grp = threadIdx.x >> 4;
    float s = 0.f, q = 0.f;
    for (int row = blockIdx.x * 16 + grp; row < NN; row += gridDim.x * 16) {
        float v = x[row * IND + col];
        s += v; q += v * v;
    }
    __shared__ float ss[16][16], qq[16][16];
    ss[grp][col] = s; qq[grp][col] = q;
    __syncthreads();
    if (grp == 0) {
        for (int j = 1; j < 16; j++) { s += ss[j][col]; q += qq[j][col]; }
        atomicAdd(&d_sumIn[col], s);
        atomicAdd(&d_sqIn[col], q);
    }
}

// ---------------- prefix scan of deg (warp-shuffle) ----------------
__global__ void k_scan1() {
    __shared__ int wsum[8];
    int tid = threadIdx.x;
    int lane = tid & 31, wid = tid >> 5;
    int i = blockIdx.x * 256 + tid;
    int v = (i < NN) ? d_deg[i] : 0;
    int s = v;
#pragma unroll
    for (int o = 1; o < 32; o <<= 1) {
        int t = __shfl_up_sync(0xffffffffu, s, o);
        if (lane >= o) s += t;
    }
    if (lane == 31) wsum[wid] = s;
    __syncthreads();
    if (wid == 0 && lane < 8) {
        int w = wsum[lane];
#pragma unroll
        for (int o = 1; o < 8; o <<= 1) {
            int t = __shfl_up_sync(0xffu, w, o);
            if (lane >= o) w += t;
        }
        wsum[lane] = w;
    }
    __syncthreads();
    int base = (wid > 0) ? wsum[wid - 1] : 0;
    if (i < NN) d_off[i] = base + s - v;  // exclusive within block
    if (tid == 255) d_bsum[blockIdx.x] = wsum[7];
}

__global__ void k_scan2() {
    __shared__ int wsum[16];
    int tid = threadIdx.x;
    int lane = tid & 31, wid = tid >> 5;
    int v = (tid < SCAN_BLOCKS) ? d_bsum[tid] : 0;
    int s = v;
#pragma unroll
    for (int o = 1; o < 32; o <<= 1) {
        int t = __shfl_up_sync(0xffffffffu, s, o);
        if (lane >= o) s += t;
    }
    if (lane == 31) wsum[wid] = s;
    __syncthreads();
    if (wid == 0 && lane < 16) {
        int w = wsum[lane];
#pragma unroll
        for (int o = 1; o < 16; o <<= 1) {
            int t = __shfl_up_sync(0xffffu, w, o);
            if (lane >= o) w += t;
        }
        wsum[lane] = w;
    }
    __syncthreads();
    int base = (wid > 0) ? wsum[wid - 1] : 0;
    if (tid < 512) d_bbase[tid] = (tid < SCAN_BLOCKS) ? (base + s - v) : 0;  // exclusive
}

__global__ void k_fill(const int* __restrict__ src, const int* __restrict__ dst, int E) {
    int e = blockIdx.x * 256 + threadIdx.x;
    if (e >= E) return;
    int d = dst[e];
    int o = d_off[d] + d_bbase[d >> 8];
    int pos = atomicAdd(&d_cur[d], 1);
    d_csr[o + pos] = src[e];
}

// ---------------- Layer-1 GEMM (K=16), latency-optimized ----------------
// 2 threads per row, 256 threads = 128 rows/block. x row in registers, W in smem,
// no in-loop syncthreads, BN fold per-block.
__global__ void __launch_bounds__(256) k_gemm16(const float* __restrict__ x,
                                                const float* __restrict__ W,
                                                __half* __restrict__ gOut,
                                                const float* __restrict__ gam,
                                                const float* __restrict__ bet) {
    __shared__ __align__(16) float Wsh[16 * 64];
    __shared__ float sA[16], sC[16];
    const int tid = threadIdx.x;
    for (int i = tid; i < 1024; i += 256) Wsh[i] = W[i];
    if (tid < 16) {
        float m = d_sumIn[tid] * (1.0f / NN);
        float var = d_sqIn[tid] * (1.0f / NN) - m * m;
        float a = gam[tid] * rsqrtf(var + EPS);
        sA[tid] = a;
        sC[tid] = bet[tid] - m * a;
    }
    __syncthreads();

    const int row = blockIdx.x * 128 + (tid >> 1);
    const int half = tid & 1;
    if (row >= NN) return;

    // load + BN-transform the x row in registers
    const float4* xr = (const float4*)(x + (size_t)row * 16);
    float4 x0 = __ldg(xr), x1 = __ldg(xr + 1), x2 = __ldg(xr + 2), x3 = __ldg(xr + 3);
    float v[16];
    v[0] = fmaf(sA[0], x0.x, sC[0]);   v[1] = fmaf(sA[1], x0.y, sC[1]);
    v[2] = fmaf(sA[2], x0.z, sC[2]);   v[3] = fmaf(sA[3], x0.w, sC[3]);
    v[4] = fmaf(sA[4], x1.x, sC[4]);   v[5] = fmaf(sA[5], x1.y, sC[5]);
    v[6] = fmaf(sA[6], x1.z, sC[6]);   v[7] = fmaf(sA[7], x1.w, sC[7]);
    v[8] = fmaf(sA[8], x2.x, sC[8]);   v[9] = fmaf(sA[9], x2.y, sC[9]);
    v[10] = fmaf(sA[10], x2.z, sC[10]); v[11] = fmaf(sA[11], x2.w, sC[11]);
    v[12] = fmaf(sA[12], x3.x, sC[12]); v[13] = fmaf(sA[13], x3.y, sC[13]);
    v[14] = fmaf(sA[14], x3.z, sC[14]); v[15] = fmaf(sA[15], x3.w, sC[15]);
    unsigned long long p[16];
#pragma unroll
    for (int k = 0; k < 16; k++) p[k] = pk2(v[k]);

    // 32 output cols per thread = 16 f32x2 accumulators
    unsigned long long acc[16];
#pragma unroll
    for (int j = 0; j < 16; j++) acc[j] = 0ull;

#pragma unroll
    for (int k = 0; k < 16; k++) {
        const float* wrow = Wsh + k * 64 + half * 32;
        ulonglong2 w0 = *(const ulonglong2*)(wrow + 0);
        ulonglong2 w1 = *(const ulonglong2*)(wrow + 4);
        ulonglong2 w2 = *(const ulonglong2*)(wrow + 8);
        ulonglong2 w3 = *(const ulonglong2*)(wrow + 12);
        ulonglong2 w4 = *(const ulonglong2*)(wrow + 16);
        ulonglong2 w5 = *(const ulonglong2*)(wrow + 20);
        ulonglong2 w6 = *(const ulonglong2*)(wrow + 24);
        ulonglong2 w7 = *(const ulonglong2*)(wrow + 28);
        fma2(acc[0], p[k], w0.x);  fma2(acc[1], p[k], w0.y);
        fma2(acc[2], p[k], w1.x);  fma2(acc[3], p[k], w1.y);
        fma2(acc[4], p[k], w2.x);  fma2(acc[5], p[k], w2.y);
        fma2(acc[6], p[k], w3.x);  fma2(acc[7], p[k], w3.y);
        fma2(acc[8], p[k], w4.x);  fma2(acc[9], p[k], w4.y);
        fma2(acc[10], p[k], w5.x); fma2(acc[11], p[k], w5.y);
        fma2(acc[12], p[k], w6.x); fma2(acc[13], p[k], w6.y);
        fma2(acc[14], p[k], w7.x); fma2(acc[15], p[k], w7.y);
    }

    float dr = rsqrtf((float)d_deg[row] + 1.0f);
    __half* gp = gOut + (size_t)row * 64 + half * 32;
#pragma unroll
    for (int q = 0; q < 4; q++) {
        float f0, f1, f2, f3, f4, f5, f6, f7;
        unpk2(acc[q * 4 + 0], f0, f1);
        unpk2(acc[q * 4 + 1], f2, f3);
        unpk2(acc[q * 4 + 2], f4, f5);
        unpk2(acc[q * 4 + 3], f6, f7);
        __half2 h0 = __floats2half2_rn(f0 * dr, f1 * dr);
        __half2 h1 = __floats2half2_rn(f2 * dr, f3 * dr);
        __half2 h2 = __floats2half2_rn(f4 * dr, f5 * dr);
        __half2 h3 = __floats2half2_rn(f6 * dr, f7 * dr);
        uint4 u;
        u.x = *(unsigned*)&h0; u.y = *(unsigned*)&h1;
        u.z = *(unsigned*)&h2; u.w = *(unsigned*)&h3;
        *(uint4*)(gp + q * 8) = u;
    }
}

// ---------------- GEMM K=64 (layers 2,3): g = fp16(dis * (relu(BN(in)) @ W)) --------
__global__ void __launch_bounds__(128) k_gemm64(const __half* __restrict__ in,
                                                const float* __restrict__ W,
                                                __half* __restrict__ gOut,
                                                const float* __restrict__ sumL,
                                                const float* __restrict__ sqL,
                                                const float* __restrict__ gam,
                                                const float* __restrict__ bet) {
    constexpr int K = 64, CHUNK = 32;
    __shared__ __align__(16) float Wsh[K * 64];
    __shared__ __align__(16) float ins[CHUNK * 132];
    __shared__ float sA[64], sC[64];
    const int tid = threadIdx.x;
    const int c0 = (tid & 7) * 8;
    const int r0 = (tid >> 3) * 8;

    for (int i = tid; i < K * 64; i += 128) Wsh[i] = W[i];
    if (tid < 64) {
        float m = sumL[tid] * (1.0f / NN);
        float var = sqL[tid] * (1.0f / NN) - m * m;
        float s = gam[tid] * rsqrtf(var + EPS);
        sA[tid] = s;
        sC[tid] = bet[tid] - m * s;
    }

    const int rowBase = blockIdx.x * 128;
    const int kk = tid & (CHUNK - 1);
    unsigned long long acc[8][4];
#pragma unroll
    for (int r = 0; r < 8; r++)
#pragma unroll
        for (int c = 0; c < 4; c++) acc[r][c] = 0ull;

    for (int kc = 0; kc < 2; kc++) {
        __syncthreads();
        const int kg = kc * CHUNK + kk;
        const float t_a = sA[kg], t_c = sC[kg];
        for (int i = tid; i < 128 * CHUNK; i += 128) {
            int rl = i >> 5;
            int row = rowBase + rl;
            float v = 0.f;
            if (row < NN) {
                float u = __half2float(in[(size_t)row * K + kg]);
                v = fmaxf(fmaf(u, t_a, t_c), 0.f);
            }
            ins[kk * 132 + rl] = v;
        }
        __syncthreads();
#pragma unroll
        for (int k = 0; k < CHUNK; k++) {
            const float* wrow = Wsh + (kc * CHUNK + k) * 64;
            ulonglong2 wa = *(const ulonglong2*)(wrow + c0);
            ulonglong2 wb = *(const ulonglong2*)(wrow + c0 + 4);
            const float* vrow = ins + k * 132;
            float4 va = *(const float4*)(vrow + r0);
            float4 vb = *(const float4*)(vrow + r0 + 4);
            unsigned long long p[8] = {pk2(va.x), pk2(va.y), pk2(va.z), pk2(va.w),
                                       pk2(vb.x), pk2(vb.y), pk2(vb.z), pk2(vb.w)};
#pragma unroll
            for (int r = 0; r < 8; r++) {
                fma2(acc[r][0], p[r], wa.x);
                fma2(acc[r][1], p[r], wa.y);
                fma2(acc[r][2], p[r], wb.x);
                fma2(acc[r][3], p[r], wb.y);
            }
        }
    }

#pragma unroll
    for (int r = 0; r < 8; r++) {
        int row = rowBase + r0 + r;
        if (row < NN) {
            float dr = rsqrtf((float)d_deg[row] + 1.0f);
            float f0, f1, f2, f3, f4, f5, f6, f7;
            unpk2(acc[r][0], f0, f1);
            unpk2(acc[r][1], f2, f3);
            unpk2(acc[r][2], f4, f5);
            unpk2(acc[r][3], f6, f7);
            __half2 h0 = __floats2half2_rn(f0 * dr, f1 * dr);
            __half2 h1 = __floats2half2_rn(f2 * dr, f3 * dr);
            __half2 h2 = __floats2half2_rn(f4 * dr, f5 * dr);
            __half2 h3 = __floats2half2_rn(f6 * dr, f7 * dr);
            uint4 u;
            u.x = *(unsigned*)&h0; u.y = *(unsigned*)&h1;
            u.z = *(unsigned*)&h2; u.w = *(unsigned*)&h3;
            *(uint4*)(gOut + (size_t)row * 64 + c0) = u;
        }
    }
}

// ---------------- CSR aggregation (fp16 gather) + dis-scale + fused BN stats ----
__global__ void __launch_bounds__(256) k_agg(const uint2* __restrict__ g2,
                                             uint2* __restrict__ accH,
                                             float* __restrict__ sumOut,
                                             float* __restrict__ sqOut) {
    __shared__ float ssum[64], ssq[64];
    const int tx = threadIdx.x, ty = threadIdx.y;
    const int tid = ty * 16 + tx;
    if (tid < 64) { ssum[tid] = 0.f; ssq[tid] = 0.f; }
    __syncthreads();

    float psx = 0.f, psy = 0.f, psz = 0.f, psw = 0.f;
    float pqx = 0.f, pqy = 0.f, pqz = 0.f, pqw = 0.f;
    const int base = blockIdx.x * 64 + ty * 4;
#pragma unroll
    for (int r = 0; r < 4; r++) {
        int n = base + r;
        if (n >= NN) break;
        uint2 us = __ldg(g2 + (size_t)n * 16 + tx);  // self-loop term
        float2 fa = __half22float2(*(__half2*)&us.x);
        float2 fb = __half22float2(*(__half2*)&us.y);
        float4 a = make_float4(fa.x, fa.y, fb.x, fb.y);
        int cnt = d_deg[n];
        int beg = d_off[n] + d_bbase[n >> 8];
        int e = 0;
        for (; e + 4 <= cnt; e += 4) {
            int s0 = __ldg(d_csr + beg + e);
            int s1 = __ldg(d_csr + beg + e + 1);
            int s2 = __ldg(d_csr + beg + e + 2);
            int s3 = __ldg(d_csr + beg + e + 3);
            uint2 u0 = __ldg(g2 + (size_t)s0 * 16 + tx);
            uint2 u1 = __ldg(g2 + (size_t)s1 * 16 + tx);
            uint2 u2 = __ldg(g2 + (size_t)s2 * 16 + tx);
            uint2 u3 = __ldg(g2 + (size_t)s3 * 16 + tx);
            float2 a0 = __half22float2(*(__half2*)&u0.x), b0 = __half22float2(*(__half2*)&u0.y);
            float2 a1 = __half22float2(*(__half2*)&u1.x), b1 = __half22float2(*(__half2*)&u1.y);
            float2 a2 = __half22float2(*(__half2*)&u2.x), b2 = __half22float2(*(__half2*)&u2.y);
            float2 a3 = __half22float2(*(__half2*)&u3.x), b3 = __half22float2(*(__half2*)&u3.y);
            a.x += (a0.x + a1.x) + (a2.x + a3.x);
            a.y += (a0.y + a1.y) + (a2.y + a3.y);
            a.z += (b0.x + b1.x) + (b2.x + b3.x);
            a.w += (b0.y + b1.y) + (b2.y + b3.y);
        }
        for (; e < cnt; e++) {
            int s = __ldg(d_csr + beg + e);
            uint2 u = __ldg(g2 + (size_t)s * 16 + tx);
            float2 va = __half22float2(*(__half2*)&u.x);
            float2 vb = __half22float2(*(__half2*)&u.y);
            a.x += va.x; a.y += va.y; a.z += vb.x; a.w += vb.y;
        }
        float dr = rsqrtf((float)cnt + 1.0f);
        a.x *= dr; a.y *= dr; a.z *= dr; a.w *= dr;
        __half2 h0 = __floats2half2_rn(a.x, a.y);
        __half2 h1 = __floats2half2_rn(a.z, a.w);
        uint2 uo;
        uo.x = *(unsigned*)&h0; uo.y = *(unsigned*)&h1;
        accH[(size_t)n * 16 + tx] = uo;
        psx += a.x; psy += a.y; psz += a.z; psw += a.w;
        pqx += a.x * a.x; pqy += a.y * a.y; pqz += a.z * a.z; pqw += a.w * a.w;
    }
    int c0 = tx * 4;
    atomicAdd(&ssum[c0 + 0], psx); atomicAdd(&ssq[c0 + 0], pqx);
    atomicAdd(&ssum[c0 + 1], psy); atomicAdd(&ssq[c0 + 1], pqy);
    atomicAdd(&ssum[c0 + 2], psz); atomicAdd(&ssq[c0 + 2], pqz);
    atomicAdd(&ssum[c0 + 3], psw); atomicAdd(&ssq[c0 + 3], pqw);
    __syncthreads();
    if (tid < 64) {
        atomicAdd(sumOut + tid, ssum[tid]);
        atomicAdd(sqOut + tid, ssq[tid]);
    }
}

// ---------------- final activation + run-accumulated mean-pool scatter ----------------
__global__ void __launch_bounds__(256) k_pool(const uint2* __restrict__ accH,
                                              const int* __restrict__ bids,
                                              const float* __restrict__ sumL,
                                              const float* __restrict__ sqL,
                                              const float* __restrict__ gam,
                                              const float* __restrict__ bet) {
    __shared__ float sA[64], sC[64];
    int tid = threadIdx.x;
    if (tid < 64) {
        float m = sumL[tid] * (1.0f / NN);
        float var = sqL[tid] * (1.0f / NN) - m * m;
        float s = gam[tid] * rsqrtf(var + EPS);
        sA[tid] = s;
        sC[tid] = bet[tid] - m * s;
    }
    __syncthreads();
    int tx = tid & 15, ty = tid >> 4;
    int cb = tx * 4;
    float a0 = sA[cb], a1 = sA[cb + 1], a2 = sA[cb + 2], a3 = sA[cb + 3];
    float c0v = sC[cb], c1v = sC[cb + 1], c2v = sC[cb + 2], c3v = sC[cb + 3];
    int base = blockIdx.x * 64 + ty * 4;
    int curG = -1, runLen = 0;
    float4 acc = make_float4(0.f, 0.f, 0.f, 0.f);
#pragma unroll
    for (int r = 0; r < 4; r++) {
        int n = base + r;
        if (n >= NN) break;
        int g = __ldg(bids + n);
        uint2 u = __ldg(accH + (size_t)n * 16 + tx);
        float2 va = __half22float2(*(__half2*)&u.x);
        float2 vb = __half22float2(*(__half2*)&u.y);
        float4 o;
        o.x = fmaxf(fmaf(va.x, a0, c0v), 0.f);
        o.y = fmaxf(fmaf(va.y, a1, c1v), 0.f);
        o.z = fmaxf(fmaf(vb.x, a2, c2v), 0.f);
        o.w = fmaxf(fmaf(vb.y, a3, c3v), 0.f);
        if (g != curG) {
            if (curG >= 0) {
                float* p = d_pool + (size_t)curG * HID + cb;
                asm volatile("red.global.add.v4.f32 [%0], {%1,%2,%3,%4};"
                             :: "l"(p), "f"(acc.x), "f"(acc.y), "f"(acc.z), "f"(acc.w)
                             : "memory");
                if (tx == 0) atomicAdd(&d_cnt[curG], runLen);
            }
            curG = g; acc = o; runLen = 1;
        } else {
            acc.x += o.x; acc.y += o.y; acc.z += o.z; acc.w += o.w;
            runLen++;
        }
    }
    if (curG >= 0) {
        float* p = d_pool + (size_t)curG * HID + cb;
        asm volatile("red.global.add.v4.f32 [%0], {%1,%2,%3,%4};"
                     :: "l"(p), "f"(acc.x), "f"(acc.y), "f"(acc.z), "f"(acc.w) : "memory");
        if (tx == 0) atomicAdd(&d_cnt[curG], runLen);
    }
}

// ---------------- classifier head ----------------
__global__ void k_head(const float* __restrict__ Wc1, const float* __restrict__ bc1,
                       const float* __restrict__ Wc2, const float* __restrict__ bc2,
                       float* __restrict__ out) {
    int g = blockIdx.x, t = threadIdx.x;
    __shared__ float p[64], z[64];
    float cnt = fmaxf((float)d_cnt[g], 1.0f);
    p[t] = d_pool[g * 64 + t] / cnt;
    __syncthreads();
    float a = bc1[t];
#pragma unroll
    for (int k = 0; k < 64; k++) a = fmaf(p[k], Wc1[k * 64 + t], a);
    z[t] = fmaxf(a, 0.f);
    __syncthreads();
    if (t < 2) {
        float o = bc2[t];
#pragma unroll
        for (int k = 0; k < 64; k++) o = fmaf(z[k], Wc2[k * 2 + t], o);
        out[g * 2 + t] = o;
    }
}

// ---------------- launch ----------------
extern "C" void kernel_launch(void* const* d_in, const int* in_sizes, int n_in,
                              void* d_out, int out_size) {
    const float *x = nullptr, *bn_in_g = nullptr, *bn_in_b = nullptr;
    const float *W0 = nullptr, *W1 = nullptr, *W2 = nullptr, *Wc1 = nullptr, *Wc2 = nullptr;
    const float *sz64[10] = {nullptr};
    const float *bc2 = nullptr;
    const int *eidx = nullptr, *bids = nullptr;
    int E = 1200000;
    int c64 = 0, c4096 = 0, c16 = 0;
    for (int i = 0; i < n_in; i++) {
        int s = in_sizes[i];
        const void* p = d_in[i];
        switch (s) {
            case 1600000: x = (const float*)p; break;
            case 2400000: eidx = (const int*)p; E = s / 2; break;
            case 100000:  bids = (const int*)p; break;
            case 16:   if (c16++ == 0) bn_in_g = (const float*)p; else bn_in_b = (const float*)p; break;
            case 1024: W0 = (const float*)p; break;
            case 4096:
                if (c4096 == 0) W1 = (const float*)p;
                else if (c4096 == 1) W2 = (const float*)p;
                else Wc1 = (const float*)p;
                c4096++; break;
            case 64:  if (c64 < 10) sz64[c64] = (const float*)p; c64++; break;
            case 128: Wc2 = (const float*)p; break;
            case 2:   bc2 = (const float*)p; break;
            default: break;
        }
    }
    const float *g0 = sz64[1], *be0 = sz64[2];
    const float *g1 = sz64[4], *be1 = sz64[5];
    const float *g2 = sz64[7], *be2 = sz64[8];
    const float *bc1 = sz64[9];
    const int* srcA = eidx;
    const int* dstA = eidx + E;
    float* out = (float*)d_out;

    __half *p_g, *p_accA, *p_accB;
    float *p_sumL, *p_sqL;
    cudaGetSymbolAddress((void**)&p_g, d_g);
    cudaGetSymbolAddress((void**)&p_accA, d_accA);
    cudaGetSymbolAddress((void**)&p_accB, d_accB);
    cudaGetSymbolAddress((void**)&p_sumL, d_sumL);
    cudaGetSymbolAddress((void**)&p_sqL, d_sqL);

    static cudaStream_t s2 = nullptr;
    static cudaEvent_t evZ = nullptr, evD = nullptr, ev2 = nullptr;
    if (!s2) {
        cudaStreamCreateWithFlags(&s2, cudaStreamNonBlocking);
        cudaEventCreateWithFlags(&evZ, cudaEventDisableTiming);
        cudaEventCreateWithFlags(&evD, cudaEventDisableTiming);
        cudaEventCreateWithFlags(&ev2, cudaEventDisableTiming);
    }

    const int ZG = SCAN_BLOCKS;
    const int EG = (E + 255) / 256;
    const int GG = (NN + 127) / 128;  // 782
    const int AG = (NN + 63) / 64;    // 1563
    dim3 ablk(16, 16);

    k_zero<<<ZG, 256>>>();
    cudaEventRecord(evZ, 0);
    k_deg<<<EG, 256>>>(dstA, E);
    cudaEventRecord(evD, 0);

    // side stream: BN stats (after zero) + layer-1 GEMM (after deg) overlap CSR build
    cudaStreamWaitEvent(s2, evZ, 0);
    k_statsIn<<<256, 256, 0, s2>>>(x);
    cudaStreamWaitEvent(s2, evD, 0);
    k_gemm16<<<GG, 256, 0, s2>>>(x, W0, p_g, bn_in_g, bn_in_b);
    cudaEventRecord(ev2, s2);

    k_scan1<<<ZG, 256>>>();
    k_scan2<<<1, 512>>>();
    k_fill<<<EG, 256>>>(srcA, dstA, E);

    cudaStreamWaitEvent(0, ev2, 0);  // join

    // Layer 1 aggregation
    k_agg<<<AG, ablk>>>((const uint2*)p_g, (uint2*)p_accA, p_sumL + 0, p_sqL + 0);
    // Layer 2
    k_gemm64<<<GG, 128>>>(p_accA, W1, p_g, p_sumL + 0, p_sqL + 0, g0, be0);
    k_agg<<<AG, ablk>>>((const uint2*)p_g, (uint2*)p_accB, p_sumL + 64, p_sqL + 64);
    // Layer 3
    k_gemm64<<<GG, 128>>>(p_accB, W2, p_g, p_sumL + 64, p_sqL + 64, g1, be1);
    k_agg<<<AG, ablk>>>((const uint2*)p_g, (uint2*)p_accA, p_sumL + 128, p_sqL + 128);

    // Pool (fused layer-3 BN fold, run-accumulated) + head
    k_pool<<<AG, 256>>>((const uint2*)p_accA, bids, p_sumL + 128, p_sqL + 128, g2, be2);
    k_head<<<NG, 64>>>(Wc1, bc1, Wc2, bc2, out);
}

// round 14
// speedup vs baseline: 1.0602x; 1.0602x over previous
#include <cuda_runtime.h>
#include <cuda_fp16.h>
#include <cstdint>

#define NN 100000
#define NG 512
#define IND 16
#define HID 64
#define EPS 1e-5f
#define MAXE 1200000
#define SCAN_BLOCKS 391  // ceil(NN/256)

// ---------------- device scratch ----------------
__device__ __half d_g[NN * HID];     // dis-scaled per-node messages (fp16)
__device__ __half d_accA[NN * HID];  // aggregated features (fp16)
__device__ __half d_accB[NN * HID];
__device__ int   d_deg[NN];
__device__ int   d_off[NN];
__device__ int   d_cur[NN];
__device__ int   d_csr[MAXE];
__device__ int   d_bsum[512];
__device__ int   d_bbase[512];
__device__ float d_sumIn[IND], d_sqIn[IND];
__device__ float d_sumL[3 * HID], d_sqL[3 * HID];
__device__ float d_pool[NG * HID];
__device__ int   d_cnt[NG];

// ---------------- f32x2 helpers ----------------
__device__ __forceinline__ unsigned long long pk2(float x) {
    unsigned long long r;
    asm("mov.b64 %0,{%1,%1};" : "=l"(r) : "f"(x));
    return r;
}
__device__ __forceinline__ void fma2(unsigned long long& d, unsigned long long a,
                                     unsigned long long b) {
    asm("fma.rn.f32x2 %0,%1,%2,%0;" : "+l"(d) : "l"(a), "l"(b));
}
__device__ __forceinline__ void unpk2(unsigned long long v, float& a, float& b) {
    asm("mov.b64 {%0,%1},%2;" : "=f"(a), "=f"(b) : "l"(v));
}

// ---------------- init ----------------
__global__ void k_zero() {
    int i = blockIdx.x * 256 + threadIdx.x;
    if (i < NN) { d_deg[i] = 0; d_cur[i] = 0; }
    if (i < NG * HID) d_pool[i] = 0.f;
    if (i < NG) d_cnt[i] = 0;
    if (i < 3 * HID) { d_sumL[i] = 0.f; d_sqL[i] = 0.f; }
    if (i < IND) { d_sumIn[i] = 0.f; d_sqIn[i] = 0.f; }
}

__global__ void k_deg(const int* __restrict__ dst, int E) {
    int e = blockIdx.x * 256 + threadIdx.x;
    if (e < E) atomicAdd(&d_deg[dst[e]], 1);
}

// ---------------- input batchnorm stats over x [N,16] ----------------
__global__ void k_statsIn(const float* __restrict__ x) {
    int col = threadIdx.x & 15, grp = threadIdx.x >> 4;
    float s = 0.f, q = 0.f;
    for (int row = blockIdx.x * 16 + grp; row < NN; row += gridDim.x * 16) {
        float v = x[row * IND + col];
        s += v; q += v * v;
    }
    __shared__ float ss[16][16], qq[16][16];
    ss[grp][col] = s; qq[grp][col] = q;
    __syncthreads();
    if (grp == 0) {
        for (int j = 1; j < 16; j++) { s += ss[j][col]; q += qq[j][col]; }
        atomicAdd(&d_sumIn[col], s);
        atomicAdd(&d_sqIn[col], q);
    }
}

// ---------------- prefix scan of deg (warp-shuffle) ----------------
__global__ void k_scan1() {
    __shared__ int wsum[8];
    int tid = threadIdx.x;
    int lane = tid & 31, wid = tid >> 5;
    int i = blockIdx.x * 256 + tid;
    int v = (i < NN) ? d_deg[i] : 0;
    int s = v;
#pragma unroll
    for (int o = 1; o < 32; o <<= 1) {
        int t = __shfl_up_sync(0xffffffffu, s, o);
        if (lane >= o) s += t;
    }
    if (lane == 31) wsum[wid] = s;
    __syncthreads();
    if (wid == 0 && lane < 8) {
        int w = wsum[lane];
#pragma unroll
        for (int o = 1; o < 8; o <<= 1) {
            int t = __shfl_up_sync(0xffu, w, o);
            if (lane >= o) w += t;
        }
        wsum[lane] = w;
    }
    __syncthreads();
    int base = (wid > 0) ? wsum[wid - 1] : 0;
    if (i < NN) d_off[i] = base + s - v;  // exclusive within block
    if (tid == 255) d_bsum[blockIdx.x] = wsum[7];
}

__global__ void k_scan2() {
    __shared__ int wsum[16];
    int tid = threadIdx.x;
    int lane = tid & 31, wid = tid >> 5;
    int v = (tid < SCAN_BLOCKS) ? d_bsum[tid] : 0;
    int s = v;
#pragma unroll
    for (int o = 1; o < 32; o <<= 1) {
        int t = __shfl_up_sync(0xffffffffu, s, o);
        if (lane >= o) s += t;
    }
    if (lane == 31) wsum[wid] = s;
    __syncthreads();
    if (wid == 0 && lane < 16) {
        int w = wsum[lane];
#pragma unroll
        for (int o = 1; o < 16; o <<= 1) {
            int t = __shfl_up_sync(0xffffu, w, o);
            if (lane >= o) w += t;
        }
        wsum[lane] = w;
    }
    __syncthreads();
    int base = (wid > 0) ? wsum[wid - 1] : 0;
    if (tid < 512) d_bbase[tid] = (tid < SCAN_BLOCKS) ? (base + s - v) : 0;  // exclusive
}

__global__ void k_fill(const int* __restrict__ src, const int* __restrict__ dst, int E) {
    int e = blockIdx.x * 256 + threadIdx.x;
    if (e >= E) return;
    int d = dst[e];
    int o = d_off[d] + d_bbase[d >> 8];
    int pos = atomicAdd(&d_cur[d], 1);
    d_csr[o + pos] = src[e];
}

// ---------------- Layer-1 GEMM (K=16), conflict-free dual-copy W ----------------
// 2 threads per row, 256 threads = 128 rows/block. W split into lo/hi column
// copies with a 16B-shifted base so each LDS128's two warp addresses hit
// disjoint bank groups (no 2-way conflict).
__global__ void __launch_bounds__(256) k_gemm16(const float* __restrict__ x,
                                                const float* __restrict__ W,
                                                __half* __restrict__ gOut,
                                                const float* __restrict__ gam,
                                                const float* __restrict__ bet) {
    // [0..511] = cols 0..31 (16 k-rows x 32), pad 4 floats, [516..1027] = cols 32..63
    __shared__ __align__(16) float Wsh[1032];
    __shared__ float sA[16], sC[16];
    const int tid = threadIdx.x;
    for (int i = tid; i < 1024; i += 256) {
        int k = i >> 6, c = i & 63;
        int idx = (c < 32) ? (k * 32 + c) : (516 + k * 32 + (c - 32));
        Wsh[idx] = W[i];
    }
    if (tid < 16) {
        float m = d_sumIn[tid] * (1.0f / NN);
        float var = d_sqIn[tid] * (1.0f / NN) - m * m;
        float a = gam[tid] * rsqrtf(var + EPS);
        sA[tid] = a;
        sC[tid] = bet[tid] - m * a;
    }
    __syncthreads();

    const int row = blockIdx.x * 128 + (tid >> 1);
    const int half = tid & 1;
    if (row >= NN) return;

    // load + BN-transform the x row in registers
    const float4* xr = (const float4*)(x + (size_t)row * 16);
    float4 x0 = __ldg(xr), x1 = __ldg(xr + 1), x2 = __ldg(xr + 2), x3 = __ldg(xr + 3);
    float v[16];
    v[0] = fmaf(sA[0], x0.x, sC[0]);   v[1] = fmaf(sA[1], x0.y, sC[1]);
    v[2] = fmaf(sA[2], x0.z, sC[2]);   v[3] = fmaf(sA[3], x0.w, sC[3]);
    v[4] = fmaf(sA[4], x1.x, sC[4]);   v[5] = fmaf(sA[5], x1.y, sC[5]);
    v[6] = fmaf(sA[6], x1.z, sC[6]);   v[7] = fmaf(sA[7], x1.w, sC[7]);
    v[8] = fmaf(sA[8], x2.x, sC[8]);   v[9] = fmaf(sA[9], x2.y, sC[9]);
    v[10] = fmaf(sA[10], x2.z, sC[10]); v[11] = fmaf(sA[11], x2.w, sC[11]);
    v[12] = fmaf(sA[12], x3.x, sC[12]); v[13] = fmaf(sA[13], x3.y, sC[13]);
    v[14] = fmaf(sA[14], x3.z, sC[14]); v[15] = fmaf(sA[15], x3.w, sC[15]);
    unsigned long long p[16];
#pragma unroll
    for (int k = 0; k < 16; k++) p[k] = pk2(v[k]);

    const float* Wbase = Wsh + half * 516;  // 516 floats = 2064B -> +16B bank shift

    // 32 output cols per thread = 16 f32x2 accumulators
    unsigned long long acc[16];
#pragma unroll
    for (int j = 0; j < 16; j++) acc[j] = 0ull;

#pragma unroll
    for (int k = 0; k < 16; k++) {
        const float* wrow = Wbase + k * 32;
        ulonglong2 w0 = *(const ulonglong2*)(wrow + 0);
        ulonglong2 w1 = *(const ulonglong2*)(wrow + 4);
        ulonglong2 w2 = *(const ulonglong2*)(wrow + 8);
        ulonglong2 w3 = *(const ulonglong2*)(wrow + 12);
        ulonglong2 w4 = *(const ulonglong2*)(wrow + 16);
        ulonglong2 w5 = *(const ulonglong2*)(wrow + 20);
        ulonglong2 w6 = *(const ulonglong2*)(wrow + 24);
        ulonglong2 w7 = *(const ulonglong2*)(wrow + 28);
        fma2(acc[0], p[k], w0.x);  fma2(acc[1], p[k], w0.y);
        fma2(acc[2], p[k], w1.x);  fma2(acc[3], p[k], w1.y);
        fma2(acc[4], p[k], w2.x);  fma2(acc[5], p[k], w2.y);
        fma2(acc[6], p[k], w3.x);  fma2(acc[7], p[k], w3.y);
        fma2(acc[8], p[k], w4.x);  fma2(acc[9], p[k], w4.y);
        fma2(acc[10], p[k], w5.x); fma2(acc[11], p[k], w5.y);
        fma2(acc[12], p[k], w6.x); fma2(acc[13], p[k], w6.y);
        fma2(acc[14], p[k], w7.x); fma2(acc[15], p[k], w7.y);
    }

    float dr = rsqrtf((float)d_deg[row] + 1.0f);
    __half* gp = gOut + (size_t)row * 64 + half * 32;
#pragma unroll
    for (int q = 0; q < 4; q++) {
        float f0, f1, f2, f3, f4, f5, f6, f7;
        unpk2(acc[q * 4 + 0], f0, f1);
        unpk2(acc[q * 4 + 1], f2, f3);
        unpk2(acc[q * 4 + 2], f4, f5);
        unpk2(acc[q * 4 + 3], f6, f7);
        __half2 h0 = __floats2half2_rn(f0 * dr, f1 * dr);
        __half2 h1 = __floats2half2_rn(f2 * dr, f3 * dr);
        __half2 h2 = __floats2half2_rn(f4 * dr, f5 * dr);
        __half2 h3 = __floats2half2_rn(f6 * dr, f7 * dr);
        uint4 u;
        u.x = *(unsigned*)&h0; u.y = *(unsigned*)&h1;
        u.z = *(unsigned*)&h2; u.w = *(unsigned*)&h3;
        *(uint4*)(gp + q * 8) = u;
    }
}

// ---------------- GEMM K=64 (layers 2,3): g = fp16(dis * (relu(BN(in)) @ W)) --------
__global__ void __launch_bounds__(128) k_gemm64(const __half* __restrict__ in,
                                                const float* __restrict__ W,
                                                __half* __restrict__ gOut,
                                                const float* __restrict__ sumL,
                                                const float* __restrict__ sqL,
                                                const float* __restrict__ gam,
                                                const float* __restrict__ bet) {
    constexpr int K = 64, CHUNK = 32;
    __shared__ __align__(16) float Wsh[K * 64];
    __shared__ __align__(16) float ins[CHUNK * 132];
    __shared__ float sA[64], sC[64];
    const int tid = threadIdx.x;
    const int c0 = (tid & 7) * 8;
    const int r0 = (tid >> 3) * 8;

    for (int i = tid; i < K * 64; i += 128) Wsh[i] = W[i];
    if (tid < 64) {
        float m = sumL[tid] * (1.0f / NN);
        float var = sqL[tid] * (1.0f / NN) - m * m;
        float s = gam[tid] * rsqrtf(var + EPS);
        sA[tid] = s;
        sC[tid] = bet[tid] - m * s;
    }

    const int rowBase = blockIdx.x * 128;
    const int kk = tid & (CHUNK - 1);
    unsigned long long acc[8][4];
#pragma unroll
    for (int r = 0; r < 8; r++)
#pragma unroll
        for (int c = 0; c < 4; c++) acc[r][c] = 0ull;

    for (int kc = 0; kc < 2; kc++) {
        __syncthreads();
        const int kg = kc * CHUNK + kk;
        const float t_a = sA[kg], t_c = sC[kg];
        for (int i = tid; i < 128 * CHUNK; i += 128) {
            int rl = i >> 5;
            int row = rowBase + rl;
            float v = 0.f;
            if (row < NN) {
                float u = __half2float(in[(size_t)row * K + kg]);
                v = fmaxf(fmaf(u, t_a, t_c), 0.f);
            }
            ins[kk * 132 + rl] = v;
        }
        __syncthreads();
#pragma unroll
        for (int k = 0; k < CHUNK; k++) {
            const float* wrow = Wsh + (kc * CHUNK + k) * 64;
            ulonglong2 wa = *(const ulonglong2*)(wrow + c0);
            ulonglong2 wb = *(const ulonglong2*)(wrow + c0 + 4);
            const float* vrow = ins + k * 132;
            float4 va = *(const float4*)(vrow + r0);
            float4 vb = *(const float4*)(vrow + r0 + 4);
            unsigned long long p[8] = {pk2(va.x), pk2(va.y), pk2(va.z), pk2(va.w),
                                       pk2(vb.x), pk2(vb.y), pk2(vb.z), pk2(vb.w)};
#pragma unroll
            for (int r = 0; r < 8; r++) {
                fma2(acc[r][0], p[r], wa.x);
                fma2(acc[r][1], p[r], wa.y);
                fma2(acc[r][2], p[r], wb.x);
                fma2(acc[r][3], p[r], wb.y);
            }
        }
    }

#pragma unroll
    for (int r = 0; r < 8; r++) {
        int row = rowBase + r0 + r;
        if (row < NN) {
            float dr = rsqrtf((float)d_deg[row] + 1.0f);
            float f0, f1, f2, f3, f4, f5, f6, f7;
            unpk2(acc[r][0], f0, f1);
            unpk2(acc[r][1], f2, f3);
            unpk2(acc[r][2], f4, f5);
            unpk2(acc[r][3], f6, f7);
            __half2 h0 = __floats2half2_rn(f0 * dr, f1 * dr);
            __half2 h1 = __floats2half2_rn(f2 * dr, f3 * dr);
            __half2 h2 = __floats2half2_rn(f4 * dr, f5 * dr);
            __half2 h3 = __floats2half2_rn(f6 * dr, f7 * dr);
            uint4 u;
            u.x = *(unsigned*)&h0; u.y = *(unsigned*)&h1;
            u.z = *(unsigned*)&h2; u.w = *(unsigned*)&h3;
            *(uint4*)(gOut + (size_t)row * 64 + c0) = u;
        }
    }
}

// ---------------- CSR aggregation (fp16 gather) + dis-scale + fused BN stats ----
__global__ void __launch_bounds__(256) k_agg(const uint2* __restrict__ g2,
                                             uint2* __restrict__ accH,
                                             float* __restrict__ sumOut,
                                             float* __restrict__ sqOut) {
    __shared__ float ssum[64], ssq[64];
    const int tx = threadIdx.x, ty = threadIdx.y;
    const int tid = ty * 16 + tx;
    if (tid < 64) { ssum[tid] = 0.f; ssq[tid] = 0.f; }
    __syncthreads();

    float psx = 0.f, psy = 0.f, psz = 0.f, psw = 0.f;
    float pqx = 0.f, pqy = 0.f, pqz = 0.f, pqw = 0.f;
    const int base = blockIdx.x * 64 + ty * 4;
#pragma unroll
    for (int r = 0; r < 4; r++) {
        int n = base + r;
        if (n >= NN) break;
        uint2 us = __ldg(g2 + (size_t)n * 16 + tx);  // self-loop term
        float2 fa = __half22float2(*(__half2*)&us.x);
        float2 fb = __half22float2(*(__half2*)&us.y);
        float4 a = make_float4(fa.x, fa.y, fb.x, fb.y);
        int cnt = d_deg[n];
        int beg = d_off[n] + d_bbase[n >> 8];
        int e = 0;
        for (; e + 4 <= cnt; e += 4) {
            int s0 = __ldg(d_csr + beg + e);
            int s1 = __ldg(d_csr + beg + e + 1);
            int s2 = __ldg(d_csr + beg + e + 2);
            int s3 = __ldg(d_csr + beg + e + 3);
            uint2 u0 = __ldg(g2 + (size_t)s0 * 16 + tx);
            uint2 u1 = __ldg(g2 + (size_t)s1 * 16 + tx);
            uint2 u2 = __ldg(g2 + (size_t)s2 * 16 + tx);
            uint2 u3 = __ldg(g2 + (size_t)s3 * 16 + tx);
            float2 a0 = __half22float2(*(__half2*)&u0.x), b0 = __half22float2(*(__half2*)&u0.y);
            float2 a1 = __half22float2(*(__half2*)&u1.x), b1 = __half22float2(*(__half2*)&u1.y);
            float2 a2 = __half22float2(*(__half2*)&u2.x), b2 = __half22float2(*(__half2*)&u2.y);
            float2 a3 = __half22float2(*(__half2*)&u3.x), b3 = __half22float2(*(__half2*)&u3.y);
            a.x += (a0.x + a1.x) + (a2.x + a3.x);
            a.y += (a0.y + a1.y) + (a2.y + a3.y);
            a.z += (b0.x + b1.x) + (b2.x + b3.x);
            a.w += (b0.y + b1.y) + (b2.y + b3.y);
        }
        for (; e < cnt; e++) {
            int s = __ldg(d_csr + beg + e);
            uint2 u = __ldg(g2 + (size_t)s * 16 + tx);
            float2 va = __half22float2(*(__half2*)&u.x);
            float2 vb = __half22float2(*(__half2*)&u.y);
            a.x += va.x; a.y += va.y; a.z += vb.x; a.w += vb.y;
        }
        float dr = rsqrtf((float)cnt + 1.0f);
        a.x *= dr; a.y *= dr; a.z *= dr; a.w *= dr;
        __half2 h0 = __floats2half2_rn(a.x, a.y);
        __half2 h1 = __floats2half2_rn(a.z, a.w);
        uint2 uo;
        uo.x = *(unsigned*)&h0; uo.y = *(unsigned*)&h1;
        accH[(size_t)n * 16 + tx] = uo;
        psx += a.x; psy += a.y; psz += a.z; psw += a.w;
        pqx += a.x * a.x; pqy += a.y * a.y; pqz += a.z * a.z; pqw += a.w * a.w;
    }
    int c0 = tx * 4;
    atomicAdd(&ssum[c0 + 0], psx); atomicAdd(&ssq[c0 + 0], pqx);
    atomicAdd(&ssum[c0 + 1], psy); atomicAdd(&ssq[c0 + 1], pqy);
    atomicAdd(&ssum[c0 + 2], psz); atomicAdd(&ssq[c0 + 2], pqz);
    atomicAdd(&ssum[c0 + 3], psw); atomicAdd(&ssq[c0 + 3], pqw);
    __syncthreads();
    if (tid < 64) {
        atomicAdd(sumOut + tid, ssum[tid]);
        atomicAdd(sqOut + tid, ssq[tid]);
    }
}

// ---------------- final activation + run-accumulated mean-pool scatter ----------------
__global__ void __launch_bounds__(256) k_pool(const uint2* __restrict__ accH,
                                              const int* __restrict__ bids,
                                              const float* __restrict__ sumL,
                                              const float* __restrict__ sqL,
                                              const float* __restrict__ gam,
                                              const float* __restrict__ bet) {
    __shared__ float sA[64], sC[64];
    int tid = threadIdx.x;
    if (tid < 64) {
        float m = sumL[tid] * (1.0f / NN);
        float var = sqL[tid] * (1.0f / NN) - m * m;
        float s = gam[tid] * rsqrtf(var + EPS);
        sA[tid] = s;
        sC[tid] = bet[tid] - m * s;
    }
    __syncthreads();
    int tx = tid & 15, ty = tid >> 4;
    int cb = tx * 4;
    float a0 = sA[cb], a1 = sA[cb + 1], a2 = sA[cb + 2], a3 = sA[cb + 3];
    float c0v = sC[cb], c1v = sC[cb + 1], c2v = sC[cb + 2], c3v = sC[cb + 3];
    int base = blockIdx.x * 64 + ty * 4;
    int curG = -1, runLen = 0;
    float4 acc = make_float4(0.f, 0.f, 0.f, 0.f);
#pragma unroll
    for (int r = 0; r < 4; r++) {
        int n = base + r;
        if (n >= NN) break;
        int g = __ldg(bids + n);
        uint2 u = __ldg(accH + (size_t)n * 16 + tx);
        float2 va = __half22float2(*(__half2*)&u.x);
        float2 vb = __half22float2(*(__half2*)&u.y);
        float4 o;
        o.x = fmaxf(fmaf(va.x, a0, c0v), 0.f);
        o.y = fmaxf(fmaf(va.y, a1, c1v), 0.f);
        o.z = fmaxf(fmaf(vb.x, a2, c2v), 0.f);
        o.w = fmaxf(fmaf(vb.y, a3, c3v), 0.f);
        if (g != curG) {
            if (curG >= 0) {
                float* p = d_pool + (size_t)curG * HID + cb;
                asm volatile("red.global.add.v4.f32 [%0], {%1,%2,%3,%4};"
                             :: "l"(p), "f"(acc.x), "f"(acc.y), "f"(acc.z), "f"(acc.w)
                             : "memory");
                if (tx == 0) atomicAdd(&d_cnt[curG], runLen);
            }
            curG = g; acc = o; runLen = 1;
        } else {
            acc.x += o.x; acc.y += o.y; acc.z += o.z; acc.w += o.w;
            runLen++;
        }
    }
    if (curG >= 0) {
        float* p = d_pool + (size_t)curG * HID + cb;
        asm volatile("red.global.add.v4.f32 [%0], {%1,%2,%3,%4};"
                     :: "l"(p), "f"(acc.x), "f"(acc.y), "f"(acc.z), "f"(acc.w) : "memory");
        if (tx == 0) atomicAdd(&d_cnt[curG], runLen);
    }
}

// ---------------- classifier head ----------------
__global__ void k_head(const float* __restrict__ Wc1, const float* __restrict__ bc1,
                       const float* __restrict__ Wc2, const float* __restrict__ bc2,
                       float* __restrict__ out) {
    int g = blockIdx.x, t = threadIdx.x;
    __shared__ float p[64], z[64];
    float cnt = fmaxf((float)d_cnt[g], 1.0f);
    p[t] = d_pool[g * 64 + t] / cnt;
    __syncthreads();
    float a = bc1[t];
#pragma unroll
    for (int k = 0; k < 64; k++) a = fmaf(p[k], Wc1[k * 64 + t], a);
    z[t] = fmaxf(a, 0.f);
    __syncthreads();
    if (t < 2) {
        float o = bc2[t];
#pragma unroll
        for (int k = 0; k < 64; k++) o = fmaf(z[k], Wc2[k * 2 + t], o);
        out[g * 2 + t] = o;
    }
}

// ---------------- launch ----------------
extern "C" void kernel_launch(void* const* d_in, const int* in_sizes, int n_in,
                              void* d_out, int out_size) {
    const float *x = nullptr, *bn_in_g = nullptr, *bn_in_b = nullptr;
    const float *W0 = nullptr, *W1 = nullptr, *W2 = nullptr, *Wc1 = nullptr, *Wc2 = nullptr;
    const float *sz64[10] = {nullptr};
    const float *bc2 = nullptr;
    const int *eidx = nullptr, *bids = nullptr;
    int E = 1200000;
    int c64 = 0, c4096 = 0, c16 = 0;
    for (int i = 0; i < n_in; i++) {
        int s = in_sizes[i];
        const void* p = d_in[i];
        switch (s) {
            case 1600000: x = (const float*)p; break;
            case 2400000: eidx = (const int*)p; E = s / 2; break;
            case 100000:  bids = (const int*)p; break;
            case 16:   if (c16++ == 0) bn_in_g = (const float*)p; else bn_in_b = (const float*)p; break;
            case 1024: W0 = (const float*)p; break;
            case 4096:
                if (c4096 == 0) W1 = (const float*)p;
                else if (c4096 == 1) W2 = (const float*)p;
                else Wc1 = (const float*)p;
                c4096++; break;
            case 64:  if (c64 < 10) sz64[c64] = (const float*)p; c64++; break;
            case 128: Wc2 = (const float*)p; break;
            case 2:   bc2 = (const float*)p; break;
            default: break;
        }
    }
    const float *g0 = sz64[1], *be0 = sz64[2];
    const float *g1 = sz64[4], *be1 = sz64[5];
    const float *g2 = sz64[7], *be2 = sz64[8];
    const float *bc1 = sz64[9];
    const int* srcA = eidx;
    const int* dstA = eidx + E;
    float* out = (float*)d_out;

    __half *p_g, *p_accA, *p_accB;
    float *p_sumL, *p_sqL;
    cudaGetSymbolAddress((void**)&p_g, d_g);
    cudaGetSymbolAddress((void**)&p_accA, d_accA);
    cudaGetSymbolAddress((void**)&p_accB, d_accB);
    cudaGetSymbolAddress((void**)&p_sumL, d_sumL);
    cudaGetSymbolAddress((void**)&p_sqL, d_sqL);

    static cudaStream_t s2 = nullptr;
    static cudaEvent_t evZ = nullptr, evD = nullptr, ev2 = nullptr;
    if (!s2) {
        cudaStreamCreateWithFlags(&s2, cudaStreamNonBlocking);
        cudaEventCreateWithFlags(&evZ, cudaEventDisableTiming);
        cudaEventCreateWithFlags(&evD, cudaEventDisableTiming);
        cudaEventCreateWithFlags(&ev2, cudaEventDisableTiming);
    }

    const int ZG = SCAN_BLOCKS;
    const int EG = (E + 255) / 256;
    const int GG = (NN + 127) / 128;  // 782
    const int AG = (NN + 63) / 64;    // 1563
    dim3 ablk(16, 16);

    k_zero<<<ZG, 256>>>();
    cudaEventRecord(evZ, 0);
    k_deg<<<EG, 256>>>(dstA, E);
    cudaEventRecord(evD, 0);

    // side stream: BN stats (after zero) + layer-1 GEMM (after deg) overlap CSR build
    cudaStreamWaitEvent(s2, evZ, 0);
    k_statsIn<<<256, 256, 0, s2>>>(x);
    cudaStreamWaitEvent(s2, evD, 0);
    k_gemm16<<<GG, 256, 0, s2>>>(x, W0, p_g, bn_in_g, bn_in_b);
    cudaEventRecord(ev2, s2);

    k_scan1<<<ZG, 256>>>();
    k_scan2<<<1, 512>>>();
    k_fill<<<EG, 256>>>(srcA, dstA, E);

    cudaStreamWaitEvent(0, ev2, 0);  // join

    // Layer 1 aggregation
    k_agg<<<AG, ablk>>>((const uint2*)p_g, (uint2*)p_accA, p_sumL + 0, p_sqL + 0);
    // Layer 2
    k_gemm64<<<GG, 128>>>(p_accA, W1, p_g, p_sumL + 0, p_sqL + 0, g0, be0);
    k_agg<<<AG, ablk>>>((const uint2*)p_g, (uint2*)p_accB, p_sumL + 64, p_sqL + 64);
    // Layer 3
    k_gemm64<<<GG, 128>>>(p_accB, W2, p_g, p_sumL + 64, p_sqL + 64, g1, be1);
    k_agg<<<AG, ablk>>>((const uint2*)p_g, (uint2*)p_accA, p_sumL + 128, p_sqL + 128);

    // Pool (fused layer-3 BN fold, run-accumulated) + head
    k_pool<<<AG, 256>>>((const uint2*)p_accA, bids, p_sumL + 128, p_sqL + 128, g2, be2);
    k_head<<<NG, 64>>>(Wc1, bc1, Wc2, bc2, out);
}

// round 15
// speedup vs baseline: 1.0834x; 1.0218x over previous
#include <cuda_runtime.h>
#include <cuda_fp16.h>
#include <cstdint>

#define NN 100000
#define NG 512
#define IND 16
#define HID 64
#define EPS 1e-5f
#define MAXE 1200000
#define SCAN_BLOCKS 391  // ceil(NN/256)

// ---------------- device scratch ----------------
__device__ __half d_g[NN * HID];     // dis-scaled per-node messages (fp16)
__device__ __half d_accA[NN * HID];  // aggregated features (fp16)
__device__ __half d_accB[NN * HID];
__device__ int   d_deg[NN];
__device__ int   d_off[NN];
__device__ int   d_cur[NN];
__device__ int   d_csr[MAXE];
__device__ int   d_bsum[512];
__device__ int   d_bbase[512];
__device__ float d_sumIn[IND], d_sqIn[IND];
__device__ float d_sumL[3 * HID], d_sqL[3 * HID];
__device__ float d_pool[NG * HID];
__device__ int   d_cnt[NG];

// ---------------- f32x2 helpers ----------------
__device__ __forceinline__ unsigned long long pk2(float x) {
    unsigned long long r;
    asm("mov.b64 %0,{%1,%1};" : "=l"(r) : "f"(x));
    return r;
}
__device__ __forceinline__ void fma2(unsigned long long& d, unsigned long long a,
                                     unsigned long long b) {
    asm("fma.rn.f32x2 %0,%1,%2,%0;" : "+l"(d) : "l"(a), "l"(b));
}
__device__ __forceinline__ void unpk2(unsigned long long v, float& a, float& b) {
    asm("mov.b64 {%0,%1},%2;" : "=f"(a), "=f"(b) : "l"(v));
}
// 8 halfs (uint4) -> 8 floats
__device__ __forceinline__ void h8f(uint4 u, float* f) {
    float2 t;
    t = __half22float2(*(__half2*)&u.x); f[0] = t.x; f[1] = t.y;
    t = __half22float2(*(__half2*)&u.y); f[2] = t.x; f[3] = t.y;
    t = __half22float2(*(__half2*)&u.z); f[4] = t.x; f[5] = t.y;
    t = __half22float2(*(__half2*)&u.w); f[6] = t.x; f[7] = t.y;
}

// ---------------- init ----------------
__global__ void k_zero() {
    int i = blockIdx.x * 256 + threadIdx.x;
    if (i < NN) { d_deg[i] = 0; d_cur[i] = 0; }
    if (i < NG * HID) d_pool[i] = 0.f;
    if (i < NG) d_cnt[i] = 0;
    if (i < 3 * HID) { d_sumL[i] = 0.f; d_sqL[i] = 0.f; }
    if (i < IND) { d_sumIn[i] = 0.f; d_sqIn[i] = 0.f; }
}

__global__ void k_deg(const int* __restrict__ dst, int E) {
    int e = blockIdx.x * 256 + threadIdx.x;
    if (e < E) atomicAdd(&d_deg[dst[e]], 1);
}

// ---------------- input batchnorm stats over x [N,16] ----------------
__global__ void k_statsIn(const float* __restrict__ x) {
    int col = threadIdx.x & 15, grp = threadIdx.x >> 4;
    float s = 0.f, q = 0.f;
    for (int row = blockIdx.x * 16 + grp; row < NN; row += gridDim.x * 16) {
        float v = x[row * IND + col];
        s += v; q += v * v;
    }
    __shared__ float ss[16][16], qq[16][16];
    ss[grp][col] = s; qq[grp][col] = q;
    __syncthreads();
    if (grp == 0) {
        for (int j = 1; j < 16; j++) { s += ss[j][col]; q += qq[j][col]; }
        atomicAdd(&d_sumIn[col], s);
        atomicAdd(&d_sqIn[col], q);
    }
}

// ---------------- prefix scan of deg (warp-shuffle) ----------------
__global__ void k_scan1() {
    __shared__ int wsum[8];
    int tid = threadIdx.x;
    int lane = tid & 31, wid = tid >> 5;
    int i = blockIdx.x * 256 + tid;
    int v = (i < NN) ? d_deg[i] : 0;
    int s = v;
#pragma unroll
    for (int o = 1; o < 32; o <<= 1) {
        int t = __shfl_up_sync(0xffffffffu, s, o);
        if (lane >= o) s += t;
    }
    if (lane == 31) wsum[wid] = s;
    __syncthreads();
    if (wid == 0 && lane < 8) {
        int w = wsum[lane];
#pragma unroll
        for (int o = 1; o < 8; o <<= 1) {
            int t = __shfl_up_sync(0xffu, w, o);
            if (lane >= o) w += t;
        }
        wsum[lane] = w;
    }
    __syncthreads();
    int base = (wid > 0) ? wsum[wid - 1] : 0;
    if (i < NN) d_off[i] = base + s - v;  // exclusive within block
    if (tid == 255) d_bsum[blockIdx.x] = wsum[7];
}

__global__ void k_scan2() {
    __shared__ int wsum[16];
    int tid = threadIdx.x;
    int lane = tid & 31, wid = tid >> 5;
    int v = (tid < SCAN_BLOCKS) ? d_bsum[tid] : 0;
    int s = v;
#pragma unroll
    for (int o = 1; o < 32; o <<= 1) {
        int t = __shfl_up_sync(0xffffffffu, s, o);
        if (lane >= o) s += t;
    }
    if (lane == 31) wsum[wid] = s;
    __syncthreads();
    if (wid == 0 && lane < 16) {
        int w = wsum[lane];
#pragma unroll
        for (int o = 1; o < 16; o <<= 1) {
            int t = __shfl_up_sync(0xffffu, w, o);
            if (lane >= o) w += t;
        }
        wsum[lane] = w;
    }
    __syncthreads();
    int base = (wid > 0) ? wsum[wid - 1] : 0;
    if (tid < 512) d_bbase[tid] = (tid < SCAN_BLOCKS) ? (base + s - v) : 0;  // exclusive
}

__global__ void k_fill(const int* __restrict__ src, const int* __restrict__ dst, int E) {
    int e = blockIdx.x * 256 + threadIdx.x;
    if (e >= E) return;
    int d = dst[e];
    int o = d_off[d] + d_bbase[d >> 8];
    int pos = atomicAdd(&d_cur[d], 1);
    d_csr[o + pos] = src[e];
}

// ---------------- Layer-1 GEMM (K=16), conflict-free dual-copy W ----------------
__global__ void __launch_bounds__(256) k_gemm16(const float* __restrict__ x,
                                                const float* __restrict__ W,
                                                __half* __restrict__ gOut,
                                                const float* __restrict__ gam,
                                                const float* __restrict__ bet) {
    // [0..511] = cols 0..31 (16 k-rows x 32), pad 4 floats, [516..1027] = cols 32..63
    __shared__ __align__(16) float Wsh[1032];
    __shared__ float sA[16], sC[16];
    const int tid = threadIdx.x;
    for (int i = tid; i < 1024; i += 256) {
        int k = i >> 6, c = i & 63;
        int idx = (c < 32) ? (k * 32 + c) : (516 + k * 32 + (c - 32));
        Wsh[idx] = W[i];
    }
    if (tid < 16) {
        float m = d_sumIn[tid] * (1.0f / NN);
        float var = d_sqIn[tid] * (1.0f / NN) - m * m;
        float a = gam[tid] * rsqrtf(var + EPS);
        sA[tid] = a;
        sC[tid] = bet[tid] - m * a;
    }
    __syncthreads();

    const int row = blockIdx.x * 128 + (tid >> 1);
    const int half = tid & 1;
    if (row >= NN) return;

    const float4* xr = (const float4*)(x + (size_t)row * 16);
    float4 x0 = __ldg(xr), x1 = __ldg(xr + 1), x2 = __ldg(xr + 2), x3 = __ldg(xr + 3);
    float v[16];
    v[0] = fmaf(sA[0], x0.x, sC[0]);   v[1] = fmaf(sA[1], x0.y, sC[1]);
    v[2] = fmaf(sA[2], x0.z, sC[2]);   v[3] = fmaf(sA[3], x0.w, sC[3]);
    v[4] = fmaf(sA[4], x1.x, sC[4]);   v[5] = fmaf(sA[5], x1.y, sC[5]);
    v[6] = fmaf(sA[6], x1.z, sC[6]);   v[7] = fmaf(sA[7], x1.w, sC[7]);
    v[8] = fmaf(sA[8], x2.x, sC[8]);   v[9] = fmaf(sA[9], x2.y, sC[9]);
    v[10] = fmaf(sA[10], x2.z, sC[10]); v[11] = fmaf(sA[11], x2.w, sC[11]);
    v[12] = fmaf(sA[12], x3.x, sC[12]); v[13] = fmaf(sA[13], x3.y, sC[13]);
    v[14] = fmaf(sA[14], x3.z, sC[14]); v[15] = fmaf(sA[15], x3.w, sC[15]);
    unsigned long long p[16];
#pragma unroll
    for (int k = 0; k < 16; k++) p[k] = pk2(v[k]);

    const float* Wbase = Wsh + half * 516;  // +2064B -> disjoint bank groups

    unsigned long long acc[16];
#pragma unroll
    for (int j = 0; j < 16; j++) acc[j] = 0ull;

#pragma unroll
    for (int k = 0; k < 16; k++) {
        const float* wrow = Wbase + k * 32;
        ulonglong2 w0 = *(const ulonglong2*)(wrow + 0);
        ulonglong2 w1 = *(const ulonglong2*)(wrow + 4);
        ulonglong2 w2 = *(const ulonglong2*)(wrow + 8);
        ulonglong2 w3 = *(const ulonglong2*)(wrow + 12);
        ulonglong2 w4 = *(const ulonglong2*)(wrow + 16);
        ulonglong2 w5 = *(const ulonglong2*)(wrow + 20);
        ulonglong2 w6 = *(const ulonglong2*)(wrow + 24);
        ulonglong2 w7 = *(const ulonglong2*)(wrow + 28);
        fma2(acc[0], p[k], w0.x);  fma2(acc[1], p[k], w0.y);
        fma2(acc[2], p[k], w1.x);  fma2(acc[3], p[k], w1.y);
        fma2(acc[4], p[k], w2.x);  fma2(acc[5], p[k], w2.y);
        fma2(acc[6], p[k], w3.x);  fma2(acc[7], p[k], w3.y);
        fma2(acc[8], p[k], w4.x);  fma2(acc[9], p[k], w4.y);
        fma2(acc[10], p[k], w5.x); fma2(acc[11], p[k], w5.y);
        fma2(acc[12], p[k], w6.x); fma2(acc[13], p[k], w6.y);
        fma2(acc[14], p[k], w7.x); fma2(acc[15], p[k], w7.y);
    }

    float dr = rsqrtf((float)d_deg[row] + 1.0f);
    __half* gp = gOut + (size_t)row * 64 + half * 32;
#pragma unroll
    for (int q = 0; q < 4; q++) {
        float f0, f1, f2, f3, f4, f5, f6, f7;
        unpk2(acc[q * 4 + 0], f0, f1);
        unpk2(acc[q * 4 + 1], f2, f3);
        unpk2(acc[q * 4 + 2], f4, f5);
        unpk2(acc[q * 4 + 3], f6, f7);
        __half2 h0 = __floats2half2_rn(f0 * dr, f1 * dr);
        __half2 h1 = __floats2half2_rn(f2 * dr, f3 * dr);
        __half2 h2 = __floats2half2_rn(f4 * dr, f5 * dr);
        __half2 h3 = __floats2half2_rn(f6 * dr, f7 * dr);
        uint4 u;
        u.x = *(unsigned*)&h0; u.y = *(unsigned*)&h1;
        u.z = *(unsigned*)&h2; u.w = *(unsigned*)&h3;
        *(uint4*)(gp + q * 8) = u;
    }
}

// ---------------- GEMM K=64 (layers 2,3): g = fp16(dis * (relu(BN(in)) @ W)) --------
__global__ void __launch_bounds__(128) k_gemm64(const __half* __restrict__ in,
                                                const float* __restrict__ W,
                                                __half* __restrict__ gOut,
                                                const float* __restrict__ sumL,
                                                const float* __restrict__ sqL,
                                                const float* __restrict__ gam,
                                                const float* __restrict__ bet) {
    constexpr int K = 64, CHUNK = 32;
    __shared__ __align__(16) float Wsh[K * 64];
    __shared__ __align__(16) float ins[CHUNK * 132];
    __shared__ float sA[64], sC[64];
    const int tid = threadIdx.x;
    const int c0 = (tid & 7) * 8;
    const int r0 = (tid >> 3) * 8;

    for (int i = tid; i < K * 64; i += 128) Wsh[i] = W[i];
    if (tid < 64) {
        float m = sumL[tid] * (1.0f / NN);
        float var = sqL[tid] * (1.0f / NN) - m * m;
        float s = gam[tid] * rsqrtf(var + EPS);
        sA[tid] = s;
        sC[tid] = bet[tid] - m * s;
    }

    const int rowBase = blockIdx.x * 128;
    const int kk = tid & (CHUNK - 1);
    unsigned long long acc[8][4];
#pragma unroll
    for (int r = 0; r < 8; r++)
#pragma unroll
        for (int c = 0; c < 4; c++) acc[r][c] = 0ull;

    for (int kc = 0; kc < 2; kc++) {
        __syncthreads();
        const int kg = kc * CHUNK + kk;
        const float t_a = sA[kg], t_c = sC[kg];
        for (int i = tid; i < 128 * CHUNK; i += 128) {
            int rl = i >> 5;
            int row = rowBase + rl;
            float v = 0.f;
            if (row < NN) {
                float u = __half2float(in[(size_t)row * K + kg]);
                v = fmaxf(fmaf(u, t_a, t_c), 0.f);
            }
            ins[kk * 132 + rl] = v;
        }
        __syncthreads();
#pragma unroll
        for (int k = 0; k < CHUNK; k++) {
            const float* wrow = Wsh + (kc * CHUNK + k) * 64;
            ulonglong2 wa = *(const ulonglong2*)(wrow + c0);
            ulonglong2 wb = *(const ulonglong2*)(wrow + c0 + 4);
            const float* vrow = ins + k * 132;
            float4 va = *(const float4*)(vrow + r0);
            float4 vb = *(const float4*)(vrow + r0 + 4);
            unsigned long long p[8] = {pk2(va.x), pk2(va.y), pk2(va.z), pk2(va.w),
                                       pk2(vb.x), pk2(vb.y), pk2(vb.z), pk2(vb.w)};
#pragma unroll
            for (int r = 0; r < 8; r++) {
                fma2(acc[r][0], p[r], wa.x);
                fma2(acc[r][1], p[r], wa.y);
                fma2(acc[r][2], p[r], wb.x);
                fma2(acc[r][3], p[r], wb.y);
            }
        }
    }

#pragma unroll
    for (int r = 0; r < 8; r++) {
        int row = rowBase + r0 + r;
        if (row < NN) {
            float dr = rsqrtf((float)d_deg[row] + 1.0f);
            float f0, f1, f2, f3, f4, f5, f6, f7;
            unpk2(acc[r][0], f0, f1);
            unpk2(acc[r][1], f2, f3);
            unpk2(acc[r][2], f4, f5);
            unpk2(acc[r][3], f6, f7);
            __half2 h0 = __floats2half2_rn(f0 * dr, f1 * dr);
            __half2 h1 = __floats2half2_rn(f2 * dr, f3 * dr);
            __half2 h2 = __floats2half2_rn(f4 * dr, f5 * dr);
            __half2 h3 = __floats2half2_rn(f6 * dr, f7 * dr);
            uint4 u;
            u.x = *(unsigned*)&h0; u.y = *(unsigned*)&h1;
            u.z = *(unsigned*)&h2; u.w = *(unsigned*)&h3;
            *(uint4*)(gOut + (size_t)row * 64 + c0) = u;
        }
    }
}

// ---------------- CSR aggregation: 8 lanes/node, uint4 loads, 2 nodes/group ----
// Halved serial chain + halved load instruction count vs the 16-lane version.
__global__ void __launch_bounds__(256) k_agg(const uint4* __restrict__ g4,
                                             uint4* __restrict__ accH4,
                                             float* __restrict__ sumOut,
                                             float* __restrict__ sqOut) {
    __shared__ float ssum[64], ssq[64];
    const int tid = threadIdx.x;
    const int lane = tid & 7;   // feature slice: halfs [lane*8, lane*8+8)
    const int grp = tid >> 3;   // 0..31
    if (tid < 64) { ssum[tid] = 0.f; ssq[tid] = 0.f; }
    __syncthreads();

    float ps[8], pq[8];
#pragma unroll
    for (int j = 0; j < 8; j++) { ps[j] = 0.f; pq[j] = 0.f; }

    const int base = blockIdx.x * 64 + grp * 2;
#pragma unroll
    for (int r = 0; r < 2; r++) {
        int n = base + r;
        if (n >= NN) break;
        float a[8];
        h8f(__ldg(g4 + (size_t)n * 8 + lane), a);  // self-loop term
        int cnt = d_deg[n];
        int beg = d_off[n] + d_bbase[n >> 8];
        int e = 0;
        for (; e + 4 <= cnt; e += 4) {
            int s0 = __ldg(d_csr + beg + e);
            int s1 = __ldg(d_csr + beg + e + 1);
            int s2 = __ldg(d_csr + beg + e + 2);
            int s3 = __ldg(d_csr + beg + e + 3);
            uint4 u0 = __ldg(g4 + (size_t)s0 * 8 + lane);
            uint4 u1 = __ldg(g4 + (size_t)s1 * 8 + lane);
            uint4 u2 = __ldg(g4 + (size_t)s2 * 8 + lane);
            uint4 u3 = __ldg(g4 + (size_t)s3 * 8 + lane);
            float f0[8], f1[8], f2[8], f3[8];
            h8f(u0, f0); h8f(u1, f1); h8f(u2, f2); h8f(u3, f3);
#pragma unroll
            for (int j = 0; j < 8; j++) a[j] += (f0[j] + f1[j]) + (f2[j] + f3[j]);
        }
        for (; e < cnt; e++) {
            int s = __ldg(d_csr + beg + e);
            float f[8];
            h8f(__ldg(g4 + (size_t)s * 8 + lane), f);
#pragma unroll
            for (int j = 0; j < 8; j++) a[j] += f[j];
        }
        float dr = rsqrtf((float)cnt + 1.0f);
#pragma unroll
        for (int j = 0; j < 8; j++) {
            a[j] *= dr;
            ps[j] += a[j];
            pq[j] += a[j] * a[j];
        }
        __half2 h0 = __floats2half2_rn(a[0], a[1]);
        __half2 h1 = __floats2half2_rn(a[2], a[3]);
        __half2 h2 = __floats2half2_rn(a[4], a[5]);
        __half2 h3 = __floats2half2_rn(a[6], a[7]);
        uint4 uo;
        uo.x = *(unsigned*)&h0; uo.y = *(unsigned*)&h1;
        uo.z = *(unsigned*)&h2; uo.w = *(unsigned*)&h3;
        accH4[(size_t)n * 8 + lane] = uo;
    }

    // reduce across the 4 groups within each warp (same lane -> same features)
#pragma unroll
    for (int j = 0; j < 8; j++) {
        ps[j] += __shfl_xor_sync(0xffffffffu, ps[j], 8);
        ps[j] += __shfl_xor_sync(0xffffffffu, ps[j], 16);
        pq[j] += __shfl_xor_sync(0xffffffffu, pq[j], 8);
        pq[j] += __shfl_xor_sync(0xffffffffu, pq[j], 16);
    }
    if ((tid & 24) == 0) {  // one thread per lane per warp
#pragma unroll
        for (int j = 0; j < 8; j++) {
            atomicAdd(&ssum[lane * 8 + j], ps[j]);
            atomicAdd(&ssq[lane * 8 + j], pq[j]);
        }
    }
    __syncthreads();
    if (tid < 64) {
        atomicAdd(sumOut + tid, ssum[tid]);
        atomicAdd(sqOut + tid, ssq[tid]);
    }
}

// ---------------- final activation + run-accumulated mean-pool scatter ----------------
__global__ void __launch_bounds__(256) k_pool(const uint2* __restrict__ accH,
                                              const int* __restrict__ bids,
                                              const float* __restrict__ sumL,
                                              const float* __restrict__ sqL,
                                              const float* __restrict__ gam,
                                              const float* __restrict__ bet) {
    __shared__ float sA[64], sC[64];
    int tid = threadIdx.x;
    if (tid < 64) {
        float m = sumL[tid] * (1.0f / NN);
        float var = sqL[tid] * (1.0f / NN) - m * m;
        float s = gam[tid] * rsqrtf(var + EPS);
        sA[tid] = s;
        sC[tid] = bet[tid] - m * s;
    }
    __syncthreads();
    int tx = tid & 15, ty = tid >> 4;
    int cb = tx * 4;
    float a0 = sA[cb], a1 = sA[cb + 1], a2 = sA[cb + 2], a3 = sA[cb + 3];
    float c0v = sC[cb], c1v = sC[cb + 1], c2v = sC[cb + 2], c3v = sC[cb + 3];
    int base = blockIdx.x * 64 + ty * 4;
    int curG = -1, runLen = 0;
    float4 acc = make_float4(0.f, 0.f, 0.f, 0.f);
#pragma unroll
    for (int r = 0; r < 4; r++) {
        int n = base + r;
        if (n >= NN) break;
        int g = __ldg(bids + n);
        uint2 u = __ldg(accH + (size_t)n * 16 + tx);
        float2 va = __half22float2(*(__half2*)&u.x);
        float2 vb = __half22float2(*(__half2*)&u.y);
        float4 o;
        o.x = fmaxf(fmaf(va.x, a0, c0v), 0.f);
        o.y = fmaxf(fmaf(va.y, a1, c1v), 0.f);
        o.z = fmaxf(fmaf(vb.x, a2, c2v), 0.f);
        o.w = fmaxf(fmaf(vb.y, a3, c3v), 0.f);
        if (g != curG) {
            if (curG >= 0) {
                float* p = d_pool + (size_t)curG * HID + cb;
                asm volatile("red.global.add.v4.f32 [%0], {%1,%2,%3,%4};"
                             :: "l"(p), "f"(acc.x), "f"(acc.y), "f"(acc.z), "f"(acc.w)
                             : "memory");
                if (tx == 0) atomicAdd(&d_cnt[curG], runLen);
            }
            curG = g; acc = o; runLen = 1;
        } else {
            acc.x += o.x; acc.y += o.y; acc.z += o.z; acc.w += o.w;
            runLen++;
        }
    }
    if (curG >= 0) {
        float* p = d_pool + (size_t)curG * HID + cb;
        asm volatile("red.global.add.v4.f32 [%0], {%1,%2,%3,%4};"
                     :: "l"(p), "f"(acc.x), "f"(acc.y), "f"(acc.z), "f"(acc.w) : "memory");
        if (tx == 0) atomicAdd(&d_cnt[curG], runLen);
    }
}

// ---------------- classifier head ----------------
__global__ void k_head(const float* __restrict__ Wc1, const float* __restrict__ bc1,
                       const float* __restrict__ Wc2, const float* __restrict__ bc2,
                       float* __restrict__ out) {
    int g = blockIdx.x, t = threadIdx.x;
    __shared__ float p[64], z[64];
    float cnt = fmaxf((float)d_cnt[g], 1.0f);
    p[t] = d_pool[g * 64 + t] / cnt;
    __syncthreads();
    float a = bc1[t];
#pragma unroll
    for (int k = 0; k < 64; k++) a = fmaf(p[k], Wc1[k * 64 + t], a);
    z[t] = fmaxf(a, 0.f);
    __syncthreads();
    if (t < 2) {
        float o = bc2[t];
#pragma unroll
        for (int k = 0; k < 64; k++) o = fmaf(z[k], Wc2[k * 2 + t], o);
        out[g * 2 + t] = o;
    }
}

// ---------------- launch ----------------
extern "C" void kernel_launch(void* const* d_in, const int* in_sizes, int n_in,
                              void* d_out, int out_size) {
    const float *x = nullptr, *bn_in_g = nullptr, *bn_in_b = nullptr;
    const float *W0 = nullptr, *W1 = nullptr, *W2 = nullptr, *Wc1 = nullptr, *Wc2 = nullptr;
    const float *sz64[10] = {nullptr};
    const float *bc2 = nullptr;
    const int *eidx = nullptr, *bids = nullptr;
    int E = 1200000;
    int c64 = 0, c4096 = 0, c16 = 0;
    for (int i = 0; i < n_in; i++) {
        int s = in_sizes[i];
        const void* p = d_in[i];
        switch (s) {
            case 1600000: x = (const float*)p; break;
            case 2400000: eidx = (const int*)p; E = s / 2; break;
            case 100000:  bids = (const int*)p; break;
            case 16:   if (c16++ == 0) bn_in_g = (const float*)p; else bn_in_b = (const float*)p; break;
            case 1024: W0 = (const float*)p; break;
            case 4096:
                if (c4096 == 0) W1 = (const float*)p;
                else if (c4096 == 1) W2 = (const float*)p;
                else Wc1 = (const float*)p;
                c4096++; break;
            case 64:  if (c64 < 10) sz64[c64] = (const float*)p; c64++; break;
            case 128: Wc2 = (const float*)p; break;
            case 2:   bc2 = (const float*)p; break;
            default: break;
        }
    }
    const float *g0 = sz64[1], *be0 = sz64[2];
    const float *g1 = sz64[4], *be1 = sz64[5];
    const float *g2 = sz64[7], *be2 = sz64[8];
    const float *bc1 = sz64[9];
    const int* srcA = eidx;
    const int* dstA = eidx + E;
    float* out = (float*)d_out;

    __half *p_g, *p_accA, *p_accB;
    float *p_sumL, *p_sqL;
    cudaGetSymbolAddress((void**)&p_g, d_g);
    cudaGetSymbolAddress((void**)&p_accA, d_accA);
    cudaGetSymbolAddress((void**)&p_accB, d_accB);
    cudaGetSymbolAddress((void**)&p_sumL, d_sumL);
    cudaGetSymbolAddress((void**)&p_sqL, d_sqL);

    static cudaStream_t s2 = nullptr;
    static cudaEvent_t evZ = nullptr, evD = nullptr, ev2 = nullptr;
    if (!s2) {
        cudaStreamCreateWithFlags(&s2, cudaStreamNonBlocking);
        cudaEventCreateWithFlags(&evZ, cudaEventDisableTiming);
        cudaEventCreateWithFlags(&evD, cudaEventDisableTiming);
        cudaEventCreateWithFlags(&ev2, cudaEventDisableTiming);
    }

    const int ZG = SCAN_BLOCKS;
    const int EG = (E + 255) / 256;
    const int GG = (NN + 127) / 128;  // 782
    const int AG = (NN + 63) / 64;    // 1563

    k_zero<<<ZG, 256>>>();
    cudaEventRecord(evZ, 0);
    k_deg<<<EG, 256>>>(dstA, E);
    cudaEventRecord(evD, 0);

    // side stream: BN stats (after zero) + layer-1 GEMM (after deg) overlap CSR build
    cudaStreamWaitEvent(s2, evZ, 0);
    k_statsIn<<<256, 256, 0, s2>>>(x);
    cudaStreamWaitEvent(s2, evD, 0);
    k_gemm16<<<GG, 256, 0, s2>>>(x, W0, p_g, bn_in_g, bn_in_b);
    cudaEventRecord(ev2, s2);

    k_scan1<<<ZG, 256>>>();
    k_scan2<<<1, 512>>>();
    k_fill<<<EG, 256>>>(srcA, dstA, E);

    cudaStreamWaitEvent(0, ev2, 0);  // join

    // Layer 1 aggregation
    k_agg<<<AG, 256>>>((const uint4*)p_g, (uint4*)p_accA, p_sumL + 0, p_sqL + 0);
    // Layer 2
    k_gemm64<<<GG, 128>>>(p_accA, W1, p_g, p_sumL + 0, p_sqL + 0, g0, be0);
    k_agg<<<AG, 256>>>((const uint4*)p_g, (uint4*)p_accB, p_sumL + 64, p_sqL + 64);
    // Layer 3
    k_gemm64<<<GG, 128>>>(p_accB, W2, p_g, p_sumL + 64, p_sqL + 64, g1, be1);
    k_agg<<<AG, 256>>>((const uint4*)p_g, (uint4*)p_accA, p_sumL + 128, p_sqL + 128);

    // Pool (fused layer-3 BN fold, run-accumulated) + head
    k_pool<<<AG, 256>>>((const uint2*)p_accA, bids, p_sumL + 128, p_sqL + 128, g2, be2);
    k_head<<<NG, 64>>>(Wc1, bc1, Wc2, bc2, out);
}